// round 2
// baseline (speedup 1.0000x reference)
#include <cuda_runtime.h>
#include <cuda_bf16.h>
#include <math_constants.h>

#define HIDDEN 1024
#define MAX_SUBWORDS 8192
#define MAX_WORDS    8192

__device__ float g_scores[MAX_SUBWORDS];
__device__ int   g_starts[MAX_WORDS];
__device__ int   g_ends[MAX_WORDS];

// Normalize span indices to int32 regardless of whether the harness handed us
// int64 or int32 buffers. For little-endian int64 data (< 2^31), every odd
// int32 word is 0; for genuine int32 sorted starts over [0,8192) that pattern
// is impossible past the first few entries.
__global__ void convert_kernel(const void* __restrict__ starts,
                               const void* __restrict__ ends,
                               int n_words) {
    __shared__ int is64;
    if (threadIdx.x == 0) {
        const int* p = (const int*)starts;
        int checks = n_words < 64 ? n_words : 64;
        int zeros = 0;
        for (int i = 0; i < checks; i++)
            if (p[2 * i + 1] == 0) zeros++;
        is64 = (zeros == checks) ? 1 : 0;
    }
    __syncthreads();
    int stride = blockDim.x * gridDim.x;
    for (int i = blockIdx.x * blockDim.x + threadIdx.x; i < n_words; i += stride) {
        if (is64) {
            g_starts[i] = (int)((const long long*)starts)[i];
            g_ends[i]   = (int)((const long long*)ends)[i];
        } else {
            g_starts[i] = ((const int*)starts)[i];
            g_ends[i]   = ((const int*)ends)[i];
        }
    }
}

// Kernel 1: scores[s] = dot(hidden[s], w) + b. One warp per subword row.
__global__ void scores_kernel(const float* __restrict__ hs,
                              const float* __restrict__ w_attn,
                              const float* __restrict__ b_attn,
                              int n_sub) {
    int warp = (blockIdx.x * blockDim.x + threadIdx.x) >> 5;
    int lane = threadIdx.x & 31;
    if (warp >= n_sub) return;

    const float4* row = reinterpret_cast<const float4*>(hs + (size_t)warp * HIDDEN);
    const float4* wv  = reinterpret_cast<const float4*>(w_attn);

    float acc = 0.0f;
#pragma unroll
    for (int i = 0; i < HIDDEN / 128; i++) {   // 8 iters: 32 lanes * 4 floats * 8 = 1024
        float4 a = row[lane + i * 32];
        float4 c = wv[lane + i * 32];
        acc += a.x * c.x + a.y * c.y + a.z * c.z + a.w * c.w;
    }
#pragma unroll
    for (int o = 16; o > 0; o >>= 1)
        acc += __shfl_xor_sync(0xFFFFFFFFu, acc, o);

    if (lane == 0) g_scores[warp] = acc + b_attn[0];
}

// Kernel 2: one block (256 threads) per word. Each thread owns one float4 of
// the hidden dim. Softmax weights recomputed per-thread (spans are tiny; the
// scalar score loads broadcast from L1).
__global__ void pool_kernel(const float* __restrict__ hs,
                            float* __restrict__ out,
                            int n_words, int n_sub) {
    int w = blockIdx.x;
    if (w >= n_words) return;
    int s0 = g_starts[w];
    int s1 = g_ends[w];
    // defensive clamp (costs nothing; protects against any residual dtype issue)
    s0 = max(0, min(s0, n_sub - 1));
    s1 = max(s0, min(s1, n_sub - 1));
    int t = threadIdx.x;                        // 0..255

    float4* op = reinterpret_cast<float4*>(out + (size_t)w * HIDDEN);

    if (s1 == s0) {
        // Span of length 1: softmax weight is exactly 1 -> row copy.
        const float4* rp = reinterpret_cast<const float4*>(hs + (size_t)s0 * HIDDEN);
        op[t] = rp[t];
        return;
    }

    // max over span
    float m = -CUDART_INF_F;
    for (int s = s0; s <= s1; s++)
        m = fmaxf(m, g_scores[s]);

    // fused exp-sum + weighted accumulation
    float Z = 0.0f;
    float4 acc = make_float4(0.f, 0.f, 0.f, 0.f);
    for (int s = s0; s <= s1; s++) {
        float p = __expf(g_scores[s] - m);
        Z += p;
        const float4 v = reinterpret_cast<const float4*>(hs + (size_t)s * HIDDEN)[t];
        acc.x += p * v.x;
        acc.y += p * v.y;
        acc.z += p * v.z;
        acc.w += p * v.w;
    }
    float inv = 1.0f / Z;
    acc.x *= inv; acc.y *= inv; acc.z *= inv; acc.w *= inv;
    op[t] = acc;
}

extern "C" void kernel_launch(void* const* d_in, const int* in_sizes, int n_in,
                              void* d_out, int out_size) {
    const float* hs     = (const float*)d_in[0];   // [n_sub, 1024]
    const void*  starts = d_in[1];                 // [n_words] int32 or int64
    const void*  ends   = d_in[2];                 // [n_words]
    const float* w_attn = (const float*)d_in[3];   // [1024, 1]
    const float* b_attn = (const float*)d_in[4];   // [1]
    float*       out    = (float*)d_out;           // [n_words, 1024]

    int n_sub   = in_sizes[0] / HIDDEN;
    int n_words = in_sizes[1];

    convert_kernel<<<(n_words + 255) / 256, 256>>>(starts, ends, n_words);

    int warps_per_block = 8;
    int blocks1 = (n_sub + warps_per_block - 1) / warps_per_block;
    scores_kernel<<<blocks1, warps_per_block * 32>>>(hs, w_attn, b_attn, n_sub);

    pool_kernel<<<n_words, HIDDEN / 4>>>(hs, out, n_words, n_sub);
}

// round 3
// speedup vs baseline: 1.1212x; 1.1212x over previous
#include <cuda_runtime.h>
#include <cuda_bf16.h>
#include <math_constants.h>

#define HIDDEN 1024
#define CHUNK 16          // span rows scored per smem round (8 warps x 2)

// Fully fused: one block (256 threads) per word.
//  - 32-lane parallel dtype sniff (int32 vs int64 span indices)
//  - 8 warps compute span scores (1024-dot each) into smem
//  - online softmax + float4 weighted accumulation, single output write
__global__ void __launch_bounds__(256) fused_pool_kernel(
        const float* __restrict__ hs,
        const void*  __restrict__ starts_raw,
        const void*  __restrict__ ends_raw,
        const float* __restrict__ w_attn,
        float*       __restrict__ out,
        int n_words, int n_sub) {
    __shared__ float sc[CHUNK];
    __shared__ int   s_is64;

    int w = blockIdx.x;
    if (w >= n_words) return;
    int t    = threadIdx.x;       // 0..255
    int warp = t >> 5;
    int lane = t & 31;

    // ---- dtype sniff: int64-LE data (<2^31) has zero odd int32 words.
    // Check 32 pairs within the first 64 int32 slots (in-bounds for both
    // interpretations when n_words >= 64). Genuine sorted int32 starts over
    // [0,8192) cannot have all of starts[1],starts[3],...,starts[63] == 0.
    if (warp == 0) {
        const int* p = (const int*)starts_raw;
        int nchk = n_words < 64 ? (n_words >> 1) : 32;
        int zero = (lane >= nchk) || (p[2 * lane + 1] == 0);
        unsigned b = __ballot_sync(0xFFFFFFFFu, zero);
        if (lane == 0) s_is64 = (b == 0xFFFFFFFFu);
    }
    __syncthreads();

    int s0, s1;
    if (s_is64) {
        s0 = (int)((const long long*)starts_raw)[w];
        s1 = (int)((const long long*)ends_raw)[w];
    } else {
        s0 = ((const int*)starts_raw)[w];
        s1 = ((const int*)ends_raw)[w];
    }
    s0 = max(0, min(s0, n_sub - 1));
    s1 = max(s0, min(s1, n_sub - 1));

    float4* op = reinterpret_cast<float4*>(out + (size_t)w * HIDDEN);

    if (s1 == s0) {
        // Length-1 span: softmax weight is exactly 1 -> row copy.
        op[t] = reinterpret_cast<const float4*>(hs + (size_t)s0 * HIDDEN)[t];
        return;
    }

    const float4* wv = reinterpret_cast<const float4*>(w_attn);

    float  m = -CUDART_INF_F;     // running max
    float  Z = 0.0f;              // running normalizer
    float4 acc = make_float4(0.f, 0.f, 0.f, 0.f);

    for (int base = s0; base <= s1; base += CHUNK) {
        int cnt = min(CHUNK, s1 - base + 1);

        // 8 warps score rows base..base+cnt-1 (dot with w_attn; bias
        // cancels in softmax so it's skipped).
        for (int r = warp; r < cnt; r += 8) {
            const float4* row = reinterpret_cast<const float4*>(
                hs + (size_t)(base + r) * HIDDEN);
            float p = 0.0f;
#pragma unroll
            for (int i = 0; i < HIDDEN / 128; i++) {
                float4 a = row[lane + i * 32];
                float4 c = wv[lane + i * 32];
                p += a.x * c.x + a.y * c.y + a.z * c.z + a.w * c.w;
            }
#pragma unroll
            for (int o = 16; o > 0; o >>= 1)
                p += __shfl_xor_sync(0xFFFFFFFFu, p, o);
            if (lane == 0) sc[r] = p;
        }
        __syncthreads();

        // online softmax update for this chunk
        float cm = -CUDART_INF_F;
        for (int r = 0; r < cnt; r++) cm = fmaxf(cm, sc[r]);
        float nm = fmaxf(m, cm);
        float scale = __expf(m - nm);     // first chunk: exp(-inf)=0
        Z *= scale;
        acc.x *= scale; acc.y *= scale; acc.z *= scale; acc.w *= scale;

        for (int r = 0; r < cnt; r++) {
            float p = __expf(sc[r] - nm);
            Z += p;
            const float4 v = reinterpret_cast<const float4*>(
                hs + (size_t)(base + r) * HIDDEN)[t];   // L1 hit (score pass warmed it)
            acc.x += p * v.x;
            acc.y += p * v.y;
            acc.z += p * v.z;
            acc.w += p * v.w;
        }
        m = nm;
        __syncthreads();   // protect sc before next chunk overwrite
    }

    float inv = 1.0f / Z;
    acc.x *= inv; acc.y *= inv; acc.z *= inv; acc.w *= inv;
    op[t] = acc;
}

extern "C" void kernel_launch(void* const* d_in, const int* in_sizes, int n_in,
                              void* d_out, int out_size) {
    const float* hs     = (const float*)d_in[0];   // [n_sub, 1024]
    const void*  starts = d_in[1];                 // [n_words] int32 or int64
    const void*  ends   = d_in[2];                 // [n_words]
    const float* w_attn = (const float*)d_in[3];   // [1024, 1]
    float*       out    = (float*)d_out;           // [n_words, 1024]

    int n_sub   = in_sizes[0] / HIDDEN;
    int n_words = in_sizes[1];

    fused_pool_kernel<<<n_words, 256>>>(hs, starts, ends, w_attn, out,
                                        n_words, n_sub);
}